// round 10
// baseline (speedup 1.0000x reference)
#include <cuda_runtime.h>
#include <cuda.h>
#include <cuda_bf16.h>
#include <cstdint>

// KinematicWaveRouting via the scalar transfer function of the 20-segment chain.
//   y_t = y_{t-1} + u_t - sum_{j=0..9} c_j u_{t-20-j},   u = runoff * basin * 50
//   (10-tap NegBinomial kernel, renormalized + mean-matched; rel err ~1e-5)
// One warp per row, lane = 128-step chunk, warm-started 32 steps early.
// Inputs: single smem tile, 16B cp.async, consumed to regs then re-prefetched.
// Outputs: body writes y*scale quads into a SW128-swizzled 32x128B tile
// (8 STS.128/group), drained by ONE 3D TMA store per group (no STG at all).
// Fallback kernel (R9 path, scalar STG drain) if tensor-map creation fails.

#define T_LEN    4096
#define CHUNK    128
#define NCHUNK   32
#define RPB      4
#define NTAPS    10
#define TSTRIDE  36

static __device__ constexpr float CNEG[NTAPS] = {
    -0.12131640f, -0.24323419f, -0.25539590f, -0.18729032f, -0.10769194f,
    -0.05169214f, -0.02153839f, -0.00799997f, -0.00269999f, -0.00114069f
};
static __device__ constexpr float GW[9] = {
    0.87868360f, 0.63544941f, 0.38005352f, 0.19276319f, 0.08507126f,
    0.03337912f, 0.01184074f, 0.00384076f, 0.00114077f
};

__device__ __forceinline__ void cpasync16(uint32_t s, const float* g) {
    asm volatile("cp.async.cg.shared.global [%0], [%1], 16;" :: "r"(s), "l"(g) : "memory");
}
__device__ __forceinline__ void cpcommit() {
    asm volatile("cp.async.commit_group;" ::: "memory");
}
template <int N>
__device__ __forceinline__ void cpwait() {
    asm volatile("cp.async.wait_group %0;" :: "n"(N) : "memory");
}
__device__ __forceinline__ void sts128(uint32_t a, float v0, float v1, float v2, float v3) {
    asm volatile("st.shared.v4.f32 [%0], {%1, %2, %3, %4};"
                 :: "r"(a), "f"(v0), "f"(v1), "f"(v2), "f"(v3) : "memory");
}

// ---------- shared pieces ----------
#define PREFETCH(GIDX)                                                      \
    do {                                                                    \
        _Pragma("unroll")                                                   \
        for (int i = 0; i < 8; i++)                                         \
            cpasync16(INslot + i * 576, rq + i * 512 + (GIDX) * 32);        \
        cpcommit();                                                         \
    } while (0)

#define LOAD_W(W)                                                           \
    do {                                                                    \
        const float4* r4 = (const float4*)INrow;                            \
        _Pragma("unroll")                                                   \
        for (int k = 0; k < 8; k++) {                                       \
            float4 q = r4[k];                                               \
            W[4 * k] = q.x; W[4 * k + 1] = q.y;                             \
            W[4 * k + 2] = q.z; W[4 * k + 3] = q.w;                         \
        }                                                                   \
    } while (0)

#define WARM_FIR(W)                                                         \
    do {                                                                    \
        float s = 0.0f;                                                     \
        _Pragma("unroll")                                                   \
        for (int j = 12; j < 32; j++) s += W[j];                            \
        float s2 = 0.0f;                                                    \
        _Pragma("unroll")                                                   \
        for (int j = 3; j < 12; j++) s2 = fmaf(GW[11 - j], W[j], s2);       \
        y = s + s2;                                                         \
    } while (0)

// ---------------- TMA kernel ----------------
// Body quads Q0..Q1 (steps 4q..4q+3): FIR + swizzled STS.128 into OUT tile.
#define BODYQ(PREV, CUR, Q0, Q1)                                            \
    do {                                                                    \
        _Pragma("unroll")                                                   \
        for (int q = (Q0); q < (Q1); q++) {                                 \
            float vv[4];                                                    \
            _Pragma("unroll")                                               \
            for (int s = 0; s < 4; s++) {                                   \
                const int m = 4 * q + s;                                    \
                float acc = CUR[m];                                         \
                _Pragma("unroll")                                           \
                for (int j = 0; j < NTAPS; j++) {                           \
                    const int k = m - (20 + j);                             \
                    float w = (k >= 0) ? CUR[k] : PREV[32 + k];             \
                    acc = fmaf(CNEG[j], w, acc);                            \
                }                                                           \
                y += acc;                                                   \
                vv[s] = y * scale;                                          \
            }                                                               \
            sts128(swbase + ((uint32_t)(q << 4) ^ swx),                     \
                   vv[0], vv[1], vv[2], vv[3]);                             \
        }                                                                   \
    } while (0)

#define TMA_STORE_GROUP(T0)                                                 \
    do {                                                                    \
        if (lane == 0) {                                                    \
            asm volatile("fence.proxy.async.shared::cta;" ::: "memory");    \
            asm volatile(                                                   \
                "cp.async.bulk.tensor.3d.global.shared::cta.tile.bulk_group " \
                "[%0, {%1, %2, %3}], [%4];"                                 \
                :: "l"(&tmap), "r"(T0), "r"(0), "r"(row), "r"(OUTw)         \
                : "memory");                                                \
            asm volatile("cp.async.bulk.commit_group;" ::: "memory");       \
        }                                                                   \
    } while (0)

#define TMA_WAIT_READ()                                                     \
    do {                                                                    \
        if (lane == 0)                                                      \
            asm volatile("cp.async.bulk.wait_group.read 0;" ::: "memory");  \
        __syncwarp();                                                       \
    } while (0)

__global__ __launch_bounds__(128, 6)
void kw_tma_kernel(const float* __restrict__ runoff,
                   const float* __restrict__ basin,
                   int B,
                   const __grid_constant__ CUtensorMap tmap)
{
    __shared__ __align__(16) float sIN[RPB][NCHUNK * TSTRIDE];
    __shared__ float sOUT[RPB * 1024 + 256];   // RPB x 4KB tiles + 1KB align slack

    const int warp = threadIdx.x >> 5;
    const int lane = threadIdx.x & 31;
    const int row  = blockIdx.x * RPB + warp;
    if (row >= B) return;

    const uint32_t INu   = (uint32_t)__cvta_generic_to_shared(&sIN[warp][0]);
    const uint32_t INslot = INu + (lane >> 3) * 144 + (lane & 7) * 16;
    const uint32_t OUTall = ((uint32_t)__cvta_generic_to_shared(&sOUT[0]) + 1023u) & ~1023u;
    const uint32_t OUTw   = OUTall + warp * 4096;
    const uint32_t swbase = OUTw + lane * 128;
    const uint32_t swx    = (uint32_t)(lane & 7) << 4;

    const float scale = basin[row] * 50.0f;
    const float* __restrict__ rq =
        runoff + (size_t)row * T_LEN + (lane >> 3) * CHUNK + (lane & 7) * 4 - 32;
    float* INrow = &sIN[warp][lane * TSTRIDE];

    float W0[32], W1[32], y;

    // ---- warm fill (chunk 0 is all t<0 -> zeros) ----
    sIN[warp][lane] = 0.0f;
#pragma unroll
    for (int i = 0; i < 8; i++) {
        if (i == 0) { if ((lane >> 3) != 0) cpasync16(INslot, rq); }
        else cpasync16(INslot + i * 576, rq + i * 512);
    }
    cpcommit();
    cpwait<0>(); __syncwarp();
    LOAD_W(W0);
    __syncwarp();
    PREFETCH(1);                       // IN free (data in W0)
    WARM_FIR(W0);

    // ---- group 1 ----
    cpwait<0>(); __syncwarp();
    LOAD_W(W1); __syncwarp();
    BODYQ(W0, W1, 0, 2);
    PREFETCH(2);
    BODYQ(W0, W1, 2, 8);
    __syncwarp();
    TMA_STORE_GROUP(0);

    // ---- group 2 ----
    cpwait<0>(); __syncwarp();
    LOAD_W(W0); __syncwarp();
    TMA_WAIT_READ();                   // OUT tile free
    BODYQ(W1, W0, 0, 2);
    PREFETCH(3);
    BODYQ(W1, W0, 2, 8);
    __syncwarp();
    TMA_STORE_GROUP(32);

    // ---- group 3 ----
    cpwait<0>(); __syncwarp();
    LOAD_W(W1); __syncwarp();
    TMA_WAIT_READ();
    BODYQ(W0, W1, 0, 2);
    PREFETCH(4);
    BODYQ(W0, W1, 2, 8);
    __syncwarp();
    TMA_STORE_GROUP(64);

    // ---- group 4 ----
    cpwait<0>(); __syncwarp();
    LOAD_W(W0); __syncwarp();
    TMA_WAIT_READ();
    BODYQ(W1, W0, 0, 8);
    __syncwarp();
    TMA_STORE_GROUP(96);

    if (lane == 0)
        asm volatile("cp.async.bulk.wait_group 0;" ::: "memory");
}

// ---------------- fallback kernel (proven R9 path) ----------------
#define FB_GROUP_BODY(PREV, CUR, TB)                                        \
    do {                                                                    \
        _Pragma("unroll")                                                   \
        for (int m = 0; m < 32; m++) {                                      \
            float acc = CUR[m];                                             \
            _Pragma("unroll")                                               \
            for (int j = 0; j < NTAPS; j++) {                               \
                const int k = m - (20 + j);                                 \
                float w = (k >= 0) ? CUR[k] : PREV[32 + k];                 \
                acc = fmaf(CNEG[j], w, acc);                                \
            }                                                               \
            y += acc;                                                       \
            (TB)[m * TSTRIDE + lane] = y;                                   \
        }                                                                   \
    } while (0)

#define FB_DRAIN(TB, GIDX)                                                  \
    do {                                                                    \
        const float4* r4 = (const float4*)((TB) + lane * TSTRIDE);          \
        _Pragma("unroll")                                                   \
        for (int k = 0; k < 8; k++) {                                       \
            float4 v = r4[k];                                               \
            orow[(4 * k + 0) * CHUNK + ((GIDX) - 1) * 32 + lane] = v.x * scale; \
            orow[(4 * k + 1) * CHUNK + ((GIDX) - 1) * 32 + lane] = v.y * scale; \
            orow[(4 * k + 2) * CHUNK + ((GIDX) - 1) * 32 + lane] = v.z * scale; \
            orow[(4 * k + 3) * CHUNK + ((GIDX) - 1) * 32 + lane] = v.w * scale; \
        }                                                                   \
    } while (0)

#define FB_PREFETCH(TU, GIDX)                                               \
    do {                                                                    \
        _Pragma("unroll")                                                   \
        for (int i = 0; i < 8; i++)                                         \
            cpasync16((TU) + i * 576, rq + i * 512 + (GIDX) * 32);          \
        cpcommit();                                                         \
    } while (0)

__global__ __launch_bounds__(128, 6)
void kw_fallback_kernel(const float* __restrict__ runoff,
                        const float* __restrict__ basin,
                        float* __restrict__ out,
                        int B)
{
    __shared__ __align__(16) float tile[2][RPB][NCHUNK * TSTRIDE];

    const int warp = threadIdx.x >> 5;
    const int lane = threadIdx.x & 31;
    const int row  = blockIdx.x * RPB + warp;
    if (row >= B) return;

    float* X = &tile[0][warp][0];
    float* Y = &tile[1][warp][0];
    const uint32_t lslot = (uint32_t)((lane >> 3) * 144 + (lane & 7) * 16);
    const uint32_t Xu = (uint32_t)__cvta_generic_to_shared(X) + lslot;
    const uint32_t Yu = (uint32_t)__cvta_generic_to_shared(Y) + lslot;

    const float scale = basin[row] * 50.0f;
    const float* __restrict__ rq =
        runoff + (size_t)row * T_LEN + (lane >> 3) * CHUNK + (lane & 7) * 4 - 32;
    float* __restrict__ orow = out + (size_t)row * T_LEN;

    float W0[32], W1[32], y;

    X[lane] = 0.0f;
#pragma unroll
    for (int i = 0; i < 8; i++) {
        if (i == 0) { if ((lane >> 3) != 0) cpasync16(Xu, rq); }
        else cpasync16(Xu + i * 576, rq + i * 512);
    }
    cpcommit();
    FB_PREFETCH(Yu, 1);
    cpwait<1>(); __syncwarp();
    {
        const float4* r4 = (const float4*)(X + lane * TSTRIDE);
#pragma unroll
        for (int k = 0; k < 8; k++) {
            float4 q = r4[k];
            W0[4*k] = q.x; W0[4*k+1] = q.y; W0[4*k+2] = q.z; W0[4*k+3] = q.w;
        }
    }
    WARM_FIR(W0);
    __syncwarp();

    FB_PREFETCH(Xu, 2);
    cpwait<1>(); __syncwarp();
    { const float4* r4 = (const float4*)(Y + lane * TSTRIDE);
#pragma unroll
      for (int k = 0; k < 8; k++) { float4 q = r4[k];
        W1[4*k]=q.x; W1[4*k+1]=q.y; W1[4*k+2]=q.z; W1[4*k+3]=q.w; } }
    __syncwarp();
    FB_GROUP_BODY(W0, W1, Y); __syncwarp();
    FB_DRAIN(Y, 1); __syncwarp();

    FB_PREFETCH(Yu, 3);
    cpwait<1>(); __syncwarp();
    { const float4* r4 = (const float4*)(X + lane * TSTRIDE);
#pragma unroll
      for (int k = 0; k < 8; k++) { float4 q = r4[k];
        W0[4*k]=q.x; W0[4*k+1]=q.y; W0[4*k+2]=q.z; W0[4*k+3]=q.w; } }
    __syncwarp();
    FB_GROUP_BODY(W1, W0, X); __syncwarp();
    FB_DRAIN(X, 2); __syncwarp();

    FB_PREFETCH(Xu, 4);
    cpwait<1>(); __syncwarp();
    { const float4* r4 = (const float4*)(Y + lane * TSTRIDE);
#pragma unroll
      for (int k = 0; k < 8; k++) { float4 q = r4[k];
        W1[4*k]=q.x; W1[4*k+1]=q.y; W1[4*k+2]=q.z; W1[4*k+3]=q.w; } }
    __syncwarp();
    FB_GROUP_BODY(W0, W1, Y); __syncwarp();
    FB_DRAIN(Y, 3); __syncwarp();

    cpwait<0>(); __syncwarp();
    { const float4* r4 = (const float4*)(X + lane * TSTRIDE);
#pragma unroll
      for (int k = 0; k < 8; k++) { float4 q = r4[k];
        W0[4*k]=q.x; W0[4*k+1]=q.y; W0[4*k+2]=q.z; W0[4*k+3]=q.w; } }
    __syncwarp();
    FB_GROUP_BODY(W1, W0, X); __syncwarp();
    FB_DRAIN(X, 4);
}

// ---------------- host launcher ----------------
typedef CUresult (*EncodeTiledFn)(
    CUtensorMap*, CUtensorMapDataType, cuuint32_t, void*,
    const cuuint64_t*, const cuuint64_t*, const cuuint32_t*, const cuuint32_t*,
    CUtensorMapInterleave, CUtensorMapSwizzle, CUtensorMapL2promotion,
    CUtensorMapFloatOOBfill);

extern "C" void kernel_launch(void* const* d_in, const int* in_sizes, int n_in,
                              void* d_out, int out_size)
{
    const float* runoff = (const float*)d_in[0];   // (B, T) float32
    const float* basin  = (const float*)d_in[1];   // (B, 1) float32
    float* out = (float*)d_out;                    // (B, T) float32
    int B = in_sizes[1];                           // 8192
    int blocks = (B + RPB - 1) / RPB;              // 2048

    // Build the output tensor map: out viewed as [B][32 chunks][128 times],
    // box = [32 times, 32 chunks, 1], SW128-swizzled smem tile.
    void* fn = nullptr;
    cudaDriverEntryPointQueryResult qr;
    bool ok = (cudaGetDriverEntryPointByVersion("cuTensorMapEncodeTiled", &fn,
                                                12000, cudaEnableDefault, &qr)
               == cudaSuccess) && fn != nullptr;
    CUtensorMap tmap;
    if (ok) {
        cuuint64_t dims[3]    = {128, 32, (cuuint64_t)B};
        cuuint64_t strides[2] = {512, 16384};            // bytes
        cuuint32_t box[3]     = {32, 32, 1};
        cuuint32_t es[3]      = {1, 1, 1};
        ok = ((EncodeTiledFn)fn)(
                 &tmap, CU_TENSOR_MAP_DATA_TYPE_FLOAT32, 3, (void*)out,
                 dims, strides, box, es,
                 CU_TENSOR_MAP_INTERLEAVE_NONE, CU_TENSOR_MAP_SWIZZLE_128B,
                 CU_TENSOR_MAP_L2_PROMOTION_L2_128B,
                 CU_TENSOR_MAP_FLOAT_OOB_FILL_NONE) == CUDA_SUCCESS;
    }

    if (ok)
        kw_tma_kernel<<<blocks, 128>>>(runoff, basin, B, tmap);
    else
        kw_fallback_kernel<<<blocks, 128>>>(runoff, basin, out, B);
}

// round 11
// speedup vs baseline: 1.1575x; 1.1575x over previous
#include <cuda_runtime.h>
#include <cuda_bf16.h>
#include <cstdint>

// KinematicWaveRouting via the scalar transfer function of the 20-segment chain.
//   y_t = y_{t-1} + u_t - sum_{j=0..7} c_j u_{t-20-j},   u = runoff * basin * 50
//   8-tap NegBinomial kernel, TWO-moment matched: corrections at m=20/24/27
//   make sum(c)=1, sum(m c)=200/9, sum(m^2 c)=496.296296 all exact.
//   Residual is 3rd-moment only (~1e-4 >> margin to 1e-3? no: ~10x under).
// One warp per row, lane = 128-step chunk, warm-started 32 steps early.
// Inputs: 16B cp.async into chunk-major tile (stride 144B), double-buffered.
// Body: 4-step quads -> y*scale -> STS.128 in place (chunk-major).
// Drain: 8 LDS.128 + 8 STG.128 (each covers 4 fully-written 128B lines).
// All smem phases conflict-free.

#define T_LEN    4096
#define CHUNK    128
#define NCHUNK   32
#define RPB      4
#define NTAPS    8
#define TSTRIDE  36          // floats per tile row (144 bytes)

// -c'_m, m = 20..27 (two-moment matched)
static __device__ constexpr float CNEG[NTAPS] = {
    -0.12252114f, -0.24315331f, -0.25531098f, -0.18722805f,
    -0.10362058f, -0.05167495f, -0.02153122f, -0.01495978f
};
// warm-start weights g'_m = 1 - cumsum(c'), lags 20..26 (g'_27 = 0)
static __device__ constexpr float GW[7] = {
    0.87747886f, 0.63432555f, 0.37901458f, 0.19178653f,
    0.08816595f, 0.03649100f, 0.01495978f
};

__device__ __forceinline__ void cpasync16(uint32_t s, const float* g) {
    asm volatile("cp.async.cg.shared.global [%0], [%1], 16;" :: "r"(s), "l"(g) : "memory");
}
__device__ __forceinline__ void cpcommit() {
    asm volatile("cp.async.commit_group;" ::: "memory");
}
template <int N>
__device__ __forceinline__ void cpwait() {
    asm volatile("cp.async.wait_group %0;" :: "n"(N) : "memory");
}
__device__ __forceinline__ void sts128(uint32_t a, float v0, float v1, float v2, float v3) {
    asm volatile("st.shared.v4.f32 [%0], {%1, %2, %3, %4};"
                 :: "r"(a), "f"(v0), "f"(v1), "f"(v2), "f"(v3) : "memory");
}

// Prefetch group GIDX: 8 x 16B cp.async per lane; instruction i covers chunks
// 4i..4i+3. rq = rrow + (lane>>3)*CHUNK + (lane&7)*4 - 32.
#define PREFETCH(TU, GIDX)                                                  \
    do {                                                                    \
        _Pragma("unroll")                                                   \
        for (int i = 0; i < 8; i++)                                         \
            cpasync16((TU) + i * 576, rq + i * 512 + (GIDX) * 32);          \
        cpcommit();                                                         \
    } while (0)

// Load the lane's 32 inputs (own chunk row): 8 x LDS.128, conflict-free.
#define LOAD_W(W, TB)                                                       \
    do {                                                                    \
        const float4* r4 = (const float4*)((TB) + lane * TSTRIDE);          \
        _Pragma("unroll")                                                   \
        for (int k = 0; k < 8; k++) {                                       \
            float4 q = r4[k];                                               \
            W[4 * k] = q.x; W[4 * k + 1] = q.y;                             \
            W[4 * k + 2] = q.z; W[4 * k + 3] = q.w;                         \
        }                                                                   \
    } while (0)

// 32 steps as 8 quads; scaled outputs overwrite the lane's own row
// (chunk-major) via STS.128.  TROWU = u32 smem addr of the lane's row.
#define GROUP_BODY(PREV, CUR, TROWU)                                        \
    do {                                                                    \
        _Pragma("unroll")                                                   \
        for (int q = 0; q < 8; q++) {                                       \
            float vv[4];                                                    \
            _Pragma("unroll")                                               \
            for (int s = 0; s < 4; s++) {                                   \
                const int m = 4 * q + s;                                    \
                float acc = CUR[m];                                         \
                _Pragma("unroll")                                           \
                for (int j = 0; j < NTAPS; j++) {                           \
                    const int k = m - (20 + j);                             \
                    float w = (k >= 0) ? CUR[k] : PREV[32 + k];             \
                    acc = fmaf(CNEG[j], w, acc);                            \
                }                                                           \
                y += acc;                                                   \
                vv[s] = y * scale;                                          \
            }                                                               \
            sts128((TROWU) + q * 16, vv[0], vv[1], vv[2], vv[3]);           \
        }                                                                   \
    } while (0)

// Drain group GIDX: lane handles (chunk = 4k + (lane>>3), quad = lane&7):
// LDS.128 from the chunk-major tile, STG.128 covering 4 full 128B lines.
#define DRAIN(TB, GIDX)                                                     \
    do {                                                                    \
        const float* sp = (TB) + (lane >> 3) * TSTRIDE + (lane & 7) * 4;    \
        float* gp = odrain + ((GIDX) - 1) * 32;                             \
        _Pragma("unroll")                                                   \
        for (int k = 0; k < 8; k++) {                                       \
            float4 v = *(const float4*)(sp + k * 4 * TSTRIDE);              \
            *(float4*)(gp + k * 512) = v;                                   \
        }                                                                   \
    } while (0)

__global__ __launch_bounds__(128, 6)
void kinematic_wave_kernel(const float* __restrict__ runoff,
                           const float* __restrict__ basin,
                           float* __restrict__ out,
                           int B)
{
    __shared__ __align__(16) float tile[2][RPB][NCHUNK * TSTRIDE];

    const int warp = threadIdx.x >> 5;
    const int lane = threadIdx.x & 31;
    const int row  = blockIdx.x * RPB + warp;
    if (row >= B) return;

    float* X = &tile[0][warp][0];
    float* Y = &tile[1][warp][0];
    const uint32_t lslot = (uint32_t)((lane >> 3) * 144 + (lane & 7) * 16);
    const uint32_t Xu = (uint32_t)__cvta_generic_to_shared(X) + lslot;
    const uint32_t Yu = (uint32_t)__cvta_generic_to_shared(Y) + lslot;
    const uint32_t Xrow = (uint32_t)__cvta_generic_to_shared(X) + lane * 144;
    const uint32_t Yrow = (uint32_t)__cvta_generic_to_shared(Y) + lane * 144;

    const float scale = basin[row] * 50.0f;
    const float* __restrict__ rq =
        runoff + (size_t)row * T_LEN + (lane >> 3) * CHUNK + (lane & 7) * 4 - 32;
    float* __restrict__ odrain =
        out + (size_t)row * T_LEN + (lane >> 3) * CHUNK + (lane & 7) * 4;

    float W0[32], W1[32], y;

    // ---- warm fill -> X (chunk 0 is all t<0 -> zeros) ----
    X[lane] = 0.0f;                                   // chunk-0 row, float = lane
#pragma unroll
    for (int i = 0; i < 8; i++) {
        if (i == 0) { if ((lane >> 3) != 0) cpasync16(Xu, rq); }
        else cpasync16(Xu + i * 576, rq + i * 512);
    }
    cpcommit();
    PREFETCH(Yu, 1);                                  // group 1 in flight
    cpwait<1>(); __syncwarp();                        // warm batch landed
    LOAD_W(W0, X);
    // warm FIR: W0[j] = u(t0-32+j), lag = 31-j; y = outlet at t0-1 (unscaled)
    {
        float s = 0.0f;
#pragma unroll
        for (int j = 12; j < 32; j++) s += W0[j];                 // lags 0..19
        float s2 = 0.0f;
#pragma unroll
        for (int j = 5; j < 12; j++) s2 = fmaf(GW[11 - j], W0[j], s2); // lags 20..26
        y = s + s2;
    }
    __syncwarp();                                     // X fully consumed

    // ---- group 1: inputs in Y; prefetch G2 -> X ----
    PREFETCH(Xu, 2);
    cpwait<1>(); __syncwarp();
    LOAD_W(W1, Y);
    GROUP_BODY(W0, W1, Yrow);
    __syncwarp();
    DRAIN(Y, 1);
    __syncwarp();

    // ---- group 2: inputs in X; prefetch G3 -> Y ----
    PREFETCH(Yu, 3);
    cpwait<1>(); __syncwarp();
    LOAD_W(W0, X);
    GROUP_BODY(W1, W0, Xrow);
    __syncwarp();
    DRAIN(X, 2);
    __syncwarp();

    // ---- group 3: inputs in Y; prefetch G4 -> X ----
    PREFETCH(Xu, 4);
    cpwait<1>(); __syncwarp();
    LOAD_W(W1, Y);
    GROUP_BODY(W0, W1, Yrow);
    __syncwarp();
    DRAIN(Y, 3);
    __syncwarp();

    // ---- group 4: inputs in X ----
    cpwait<0>(); __syncwarp();
    LOAD_W(W0, X);
    GROUP_BODY(W1, W0, Xrow);
    __syncwarp();
    DRAIN(X, 4);
}

extern "C" void kernel_launch(void* const* d_in, const int* in_sizes, int n_in,
                              void* d_out, int out_size)
{
    const float* runoff = (const float*)d_in[0];   // (B, T) float32
    const float* basin  = (const float*)d_in[1];   // (B, 1) float32
    float* out = (float*)d_out;                    // (B, T) float32

    int B = in_sizes[1];                           // 8192
    int blocks = (B + RPB - 1) / RPB;              // 2048
    kinematic_wave_kernel<<<blocks, 128>>>(runoff, basin, out, B);
}